// round 3
// baseline (speedup 1.0000x reference)
#include <cuda_runtime.h>

typedef unsigned long long ull;

#define HH 512
#define WW 512
#define BB 16
#define RPB 8
#define GRIDX (HH / RPB)      // 64
#define NBLK  (GRIDX * BB)    // 1024
#define NTHR  256
#define FULLM 0xffffffffu

__device__ float    g_part[NBLK];
__device__ unsigned g_cnt = 0;

// ---- packed f32x2 helpers (sm_100+ FFMA2 path, PTX-only) ----
__device__ __forceinline__ ull pk(float lo, float hi) {
    ull r; asm("mov.b64 %0,{%1,%2};" : "=l"(r) : "f"(lo), "f"(hi)); return r;
}
__device__ __forceinline__ void upk(ull v, float& lo, float& hi) {
    asm("mov.b64 {%0,%1},%2;" : "=f"(lo), "=f"(hi) : "l"(v));
}
__device__ __forceinline__ ull sub2(ull a, ull b){ ull r; asm("sub.rn.f32x2 %0,%1,%2;":"=l"(r):"l"(a),"l"(b)); return r; }
__device__ __forceinline__ ull add2(ull a, ull b){ ull r; asm("add.rn.f32x2 %0,%1,%2;":"=l"(r):"l"(a),"l"(b)); return r; }
__device__ __forceinline__ ull mul2(ull a, ull b){ ull r; asm("mul.rn.f32x2 %0,%1,%2;":"=l"(r):"l"(a),"l"(b)); return r; }
__device__ __forceinline__ ull fma2(ull a, ull b, ull c){ ull r; asm("fma.rn.f32x2 %0,%1,%2,%3;":"=l"(r):"l"(a),"l"(b),"l"(c)); return r; }
__device__ __forceinline__ float ex2f(float x){ float r; asm("ex2.approx.f32 %0,%1;":"=f"(r):"f"(x)); return r; }

struct RowData {
    ull y,  a,  b,  c;     // aligned pair  (x0, x1)       at (w0, w0+1)
    ull yR, aR, bR, cR;    // right pair    (x1, xhaloR)   neighbors at +1
    ull yL, aL, bL, cL;    // left pair     (xhaloL, x0)   neighbors at -1
};

// one packed shift-term: 2 pixels at once.
// contribution = (exp(-d2/(2s^2))*wxy - eps) * (ya-yb)^2 * [mask]
template<bool MASK>
__device__ __forceinline__ void pterm(ull& acc,
        ull a0, ull a1, ull a2, ull b0, ull b1, ull b2,
        ull ya, ull yb, ull wxy, ull mask, ull c2, ull negeps)
{
    ull d0 = sub2(a0, b0), d1 = sub2(a1, b1), d2 = sub2(a2, b2);
    ull s  = mul2(d0, d0);
    s = fma2(d1, d1, s);
    s = fma2(d2, d2, s);
    s = mul2(s, c2);                 // c2 = -log2(e)/(2*sigma^2), per-lane
    float s0, s1; upk(s, s0, s1);
    ull e  = pk(ex2f(s0), ex2f(s1));
    ull m  = fma2(e, wxy, negeps);   // e*wxy - 0.01
    ull dy = sub2(ya, yb);
    ull t  = mul2(m, mul2(dy, dy));
    if (MASK) t = mul2(t, mask);
    acc = add2(acc, t);
}

__device__ __forceinline__ RowData loadrow(const float* __restrict__ Y,
                                           const float* __restrict__ A,
                                           const float* __restrict__ Bp,
                                           const float* __restrict__ Cp,
                                           int off, int lane, bool hasR, bool hasL)
{
    RowData R;
    float2 t; float xr, xl;
#define LDROW(P, alv, prv, plv)                                   \
    t  = *(const float2*)(P + off);                               \
    xr = __shfl_down_sync(FULLM, t.x, 1);                         \
    if (lane == 31) xr = hasR ? __ldg(P + off + 2) : 0.0f;        \
    xl = __shfl_up_sync(FULLM, t.y, 1);                           \
    if (lane == 0)  xl = hasL ? __ldg(P + off - 1) : 0.0f;        \
    R.alv = pk(t.x, t.y); R.prv = pk(t.y, xr); R.plv = pk(xl, t.x);
    LDROW(Y,  y, yR, yL)
    LDROW(A,  a, aR, aL)
    LDROW(Bp, b, bR, bL)
    LDROW(Cp, c, cR, cL)
#undef LDROW
    return R;
}

__global__ void __launch_bounds__(NTHR, 4)
crf_loss_kernel(const float* __restrict__ ypr,
                const float* __restrict__ img,
                const int*   __restrict__ icls,
                float* __restrict__ out)
{
    const int tid  = threadIdx.x;
    const int lane = tid & 31;
    const int bx   = blockIdx.x;
    const int b    = blockIdx.y;
    const int bid  = b * GRIDX + bx;
    const int w0   = tid << 1;               // 2 px/thread, 256 thr = full row
    const int r0   = bx * RPB;

    __shared__ float sm[NTHR / 32];
    __shared__ bool  s_last;

    float blocksum = 0.0f;                   // meaningful on tid 0

    if (icls[b] != 0) {
        const float* Y  = ypr + (size_t)(2 * b + 1) * (HH * WW);
        const float* I0 = img + (size_t)(3 * b)     * (HH * WW);
        const float* I1 = I0 + HH * WW;
        const float* I2 = I1 + HH * WW;

        const bool hasR = (w0 + 2 < WW);     // false only tid 255
        const bool hasL = (w0 > 0);          // false only tid 0

        const ull C2  = pk(-32.05988979753252f, -32.05988979753252f); // -log2e/(2*0.15^2)
        const ull NE2 = pk(-0.01f, -0.01f);
        const ull W1  = pk(0.60653065971263342f, 0.60653065971263342f); // exp(-0.5)
        const ull W2  = pk(0.36787944117144233f, 0.36787944117144233f); // exp(-1.0)
        const ull MR  = pk(1.0f, hasR ? 1.0f : 0.0f);   // masks pixel1's +1 neighbor
        const ull ML  = pk(hasL ? 1.0f : 0.0f, 1.0f);   // masks pixel0's -1 neighbor

        ull acc = 0;   // two packed +0.0f

        // prologue: row r0 + its horizontal terms
        RowData rd = loadrow(Y, I0, I1, I2, r0 * WW + w0, lane, hasR, hasL);
        pterm<true>(acc, rd.a, rd.b, rd.c, rd.aR, rd.bR, rd.cR, rd.y, rd.yR, W1, MR, C2, NE2);
        ull cy = rd.y, ca = rd.a, cb = rd.b, cc = rd.c;

#pragma unroll
        for (int rr = 0; rr < RPB; rr++) {
            const int r = r0 + rr + 1;
            if (r < HH) {                    // uniform; false only last strip, last iter
                RowData nx = loadrow(Y, I0, I1, I2, r * WW + w0, lane, hasR, hasL);
                if (rr < RPB - 1)            // next row's horizontal belongs to this strip
                    pterm<true>(acc, nx.a, nx.b, nx.c, nx.aR, nx.bR, nx.cR,
                                nx.y, nx.yR, W1, MR, C2, NE2);
                // shift (1,1): down-right   -> next row's right pair
                pterm<true>(acc, ca, cb, cc, nx.aR, nx.bR, nx.cR, cy, nx.yR, W2, MR, C2, NE2);
                // shift (1,-1): down-left   -> next row's left pair
                pterm<true>(acc, ca, cb, cc, nx.aL, nx.bL, nx.cL, cy, nx.yL, W2, ML, C2, NE2);
                // shift (1,0): aligned vertical
                pterm<false>(acc, ca, cb, cc, nx.a, nx.b, nx.c, cy, nx.y, W1, MR, C2, NE2);
                cy = nx.y; ca = nx.a; cb = nx.b; cc = nx.c;
            }
        }

        float aL0, aH0; upk(acc, aL0, aH0);
        float v = aL0 + aH0;
#pragma unroll
        for (int o = 16; o > 0; o >>= 1)
            v += __shfl_down_sync(FULLM, v, o);
        if (lane == 0) sm[tid >> 5] = v;
        __syncthreads();
        if (tid == 0) {
            float s = 0.0f;
#pragma unroll
            for (int i = 0; i < NTHR / 32; i++) s += sm[i];
            blocksum = s;
        }
    }

    // ---- single-kernel deterministic global reduction (threadfence counter) ----
    if (tid == 0) {
        g_part[bid] = blocksum;
        __threadfence();
        unsigned old = atomicInc(&g_cnt, NBLK - 1u);   // wraps to 0 each launch
        s_last = (old == NBLK - 1u);
    }
    __syncthreads();

    if (s_last) {
        float v = 0.0f;
        for (int i = tid; i < NBLK; i += NTHR)
            v += ((volatile float*)g_part)[i];
#pragma unroll
        for (int o = 16; o > 0; o >>= 1)
            v += __shfl_down_sync(FULLM, v, o);
        if (lane == 0) sm[tid >> 5] = v;
        __syncthreads();
        if (tid == 0) {
            float s = 0.0f;
#pragma unroll
            for (int i = 0; i < NTHR / 32; i++) s += sm[i];
            const float SCALE = 1.0f / 16777216.0f;    // 1/(H*W*B*4), WEIGHT=1
            out[0] = s * SCALE;
        }
    }
}

extern "C" void kernel_launch(void* const* d_in, const int* in_sizes, int n_in,
                              void* d_out, int out_size) {
    const float* ypr  = (const float*)d_in[0];   // y_pr  (16,2,512,512)
    // d_in[1] = y_gt (unused by the reference)
    const float* img  = (const float*)d_in[2];   // image (16,3,512,512)
    const int*   icls = (const int*)d_in[3];     // image_class (16,)
    float* out = (float*)d_out;

    dim3 grid(GRIDX, BB);
    crf_loss_kernel<<<grid, NTHR>>>(ypr, img, icls, out);
}